// round 1
// baseline (speedup 1.0000x reference)
#include <cuda_runtime.h>
#include <math.h>
#include <stdint.h>

// ===========================================================================
// MoE top-2 layer, sparse grouped-GEMM formulation.
//   N=16384 tokens, D=1024, H=1024, E=8 experts, TOP_K=2
//   out[n] = sum_{k in top2} p_nk * (x[n] @ W_{e_nk} + b_{e_nk})
//   loss   = 0.1 * mean(entropy(softmax(gate))) + sum_e relu(count_e/N - 0.3)
// Pipeline: zero-out -> init -> gate(softmax/top2/entropy/counts)
//           -> scan(offsets, tile list, loss) -> scatter(bucket by expert)
//           -> grouped gather-GEMM (FFMA, 128x128x16 tiles, atomicAdd combine)
// ===========================================================================

#define NEXP 8
#define TOPK 2
#define MAXN 16384
#define MAXPAIRS (MAXN * TOPK)
#define MAXTILES 272          // ceil(2N/128) + E upper bound
#define BM 128
#define BN 128
#define BK 16

// ---- device scratch (static: no allocation allowed) ----
__device__ int   g_counts[NEXP];
__device__ int   g_cursor[NEXP];
__device__ float g_ent;
__device__ int   g_topk_idx[MAXPAIRS];
__device__ float g_topk_p[MAXPAIRS];
__device__ int   g_pairs_token[MAXPAIRS];
__device__ float g_pairs_prob[MAXPAIRS];
__device__ int   g_tile_e[MAXTILES];
__device__ int   g_tile_start[MAXTILES];
__device__ int   g_tile_rows[MAXTILES];
__device__ int   g_ntiles;

// ---------------------------------------------------------------------------
__global__ void zero_out_kernel(float* __restrict__ out, size_t n4) {
    // n4 = number of float4's
    size_t i = (size_t)blockIdx.x * blockDim.x + threadIdx.x;
    size_t stride = (size_t)gridDim.x * blockDim.x;
    float4 z = make_float4(0.f, 0.f, 0.f, 0.f);
    float4* o4 = reinterpret_cast<float4*>(out);
    for (; i < n4; i += stride) o4[i] = z;
}

__global__ void init_kernel() {
    int t = threadIdx.x;
    if (t < NEXP) g_counts[t] = 0;
    if (t == 0) g_ent = 0.f;
}

// ---------------------------------------------------------------------------
// Gating: one warp per token. Computes logits = x@gate_w + gate_b, softmax,
// entropy, top-2 (jax top_k tie-break = lower index first).
__global__ void gate_kernel(const float* __restrict__ x,
                            const float* __restrict__ gw,
                            const float* __restrict__ gb,
                            int N, int D) {
    __shared__ int   s_cnt[NEXP];
    __shared__ float s_ent;
    int tid = threadIdx.x;
    if (tid < NEXP) s_cnt[tid] = 0;
    if (tid == 0) s_ent = 0.f;
    __syncthreads();

    int warp = tid >> 5, lane = tid & 31;
    int token = blockIdx.x * (blockDim.x >> 5) + warp;
    if (token < N) {
        float acc[NEXP];
#pragma unroll
        for (int e = 0; e < NEXP; e++) acc[e] = 0.f;
        const float* xr = x + (size_t)token * D;
        for (int d = lane; d < D; d += 32) {
            float xv = xr[d];
            const float4* g4 = reinterpret_cast<const float4*>(gw + (size_t)d * NEXP);
            float4 a = g4[0], b = g4[1];
            acc[0] += xv * a.x; acc[1] += xv * a.y;
            acc[2] += xv * a.z; acc[3] += xv * a.w;
            acc[4] += xv * b.x; acc[5] += xv * b.y;
            acc[6] += xv * b.z; acc[7] += xv * b.w;
        }
#pragma unroll
        for (int off = 16; off > 0; off >>= 1) {
#pragma unroll
            for (int e = 0; e < NEXP; e++)
                acc[e] += __shfl_xor_sync(0xffffffffu, acc[e], off);
        }
        if (lane == 0) {
            float l[NEXP];
            float mx = -1e30f;
#pragma unroll
            for (int e = 0; e < NEXP; e++) { l[e] = acc[e] + gb[e]; mx = fmaxf(mx, l[e]); }
            float sum = 0.f;
#pragma unroll
            for (int e = 0; e < NEXP; e++) { l[e] = __expf(l[e] - mx); sum += l[e]; }
            float inv = 1.f / sum;
            float ent = 0.f;
#pragma unroll
            for (int e = 0; e < NEXP; e++) {
                l[e] *= inv;  // now probs
                ent -= l[e] * logf(l[e] + 1e-10f);
            }
            // top-1
            int i0 = 0; float p0 = l[0];
#pragma unroll
            for (int e = 1; e < NEXP; e++) if (l[e] > p0) { p0 = l[e]; i0 = e; }
            // top-2 (exclude i0)
            int i1 = (i0 == 0) ? 1 : 0; float p1 = l[i1];
#pragma unroll
            for (int e = 0; e < NEXP; e++)
                if (e != i0 && l[e] > p1) { p1 = l[e]; i1 = e; }

            g_topk_idx[2 * token + 0] = i0;
            g_topk_idx[2 * token + 1] = i1;
            g_topk_p[2 * token + 0] = p0;
            g_topk_p[2 * token + 1] = p1;
            atomicAdd(&s_cnt[i0], 1);
            atomicAdd(&s_cnt[i1], 1);
            atomicAdd(&s_ent, ent);
        }
    }
    __syncthreads();
    if (tid < NEXP && s_cnt[tid] > 0) atomicAdd(&g_counts[tid], s_cnt[tid]);
    if (tid == 0 && s_ent != 0.f) atomicAdd(&g_ent, s_ent);
}

// ---------------------------------------------------------------------------
// Single-thread: exclusive scan, tile list, aux loss scalar.
__global__ void scan_kernel(float* __restrict__ out, long long out_size,
                            int N, int H) {
    if (threadIdx.x != 0 || blockIdx.x != 0) return;
    int off = 0, nt = 0;
    for (int e = 0; e < NEXP; e++) {
        g_cursor[e] = off;
        int c = g_counts[e];
        for (int s = 0; s < c; s += BM) {
            g_tile_e[nt] = e;
            g_tile_start[nt] = off + s;
            g_tile_rows[nt] = (c - s < BM) ? (c - s) : BM;
            nt++;
        }
        off += c;
    }
    g_ntiles = nt;

    float loss = 0.1f * (g_ent / (float)N);
    for (int e = 0; e < NEXP; e++) {
        float u = (float)g_counts[e] / (float)N - 0.3f;
        if (u > 0.f) loss += u;
    }
    if (out_size > (long long)N * (long long)H)
        out[out_size - 1] = loss;
}

// ---------------------------------------------------------------------------
// Bucket (token, prob) pairs by expert.
__global__ void scatter_kernel(int N) {
    int n = blockIdx.x * blockDim.x + threadIdx.x;
    if (n >= N) return;
#pragma unroll
    for (int k = 0; k < TOPK; k++) {
        int e = g_topk_idx[2 * n + k];
        int pos = atomicAdd(&g_cursor[e], 1);
        g_pairs_token[pos] = n;
        g_pairs_prob[pos] = g_topk_p[2 * n + k];
    }
}

// ---------------------------------------------------------------------------
// Grouped gather-GEMM: tile (128 pair-rows) x (128 H-cols), K-loop over D.
// Epilogue: out[token] += p * (acc + bias)  via atomicAdd (exactly 2 adds/elem).
__global__ __launch_bounds__(256, 2)
void moe_gemm_kernel(const float* __restrict__ x,
                     const float* __restrict__ ew,
                     const float* __restrict__ eb,
                     float* __restrict__ out,
                     int D, int H) {
    int rt = blockIdx.y;
    if (rt >= g_ntiles) return;
    const int e     = g_tile_e[rt];
    const int start = g_tile_start[rt];
    const int rows  = g_tile_rows[rt];
    const int n0    = blockIdx.x * BN;
    const float* __restrict__ W = ew + (size_t)e * D * H;

    __shared__ float As[BK][BM + 4];   // padded, 528B rows keep float4 alignment
    __shared__ float Bs[BK][BN];
    __shared__ int   sTok[BM];
    __shared__ float sP[BM];

    int tid = threadIdx.x;
    if (tid < BM) {
        if (tid < rows) {
            sTok[tid] = g_pairs_token[start + tid];
            sP[tid]   = g_pairs_prob[start + tid];
        } else {
            sTok[tid] = -1;
            sP[tid]   = 0.f;
        }
    }
    __syncthreads();

    const int tx = tid & 15;       // 0..15 -> col micro-tile
    const int ty = tid >> 4;       // 0..15 -> row micro-tile
    float acc[8][8];
#pragma unroll
    for (int i = 0; i < 8; i++)
#pragma unroll
        for (int j = 0; j < 8; j++) acc[i][j] = 0.f;

    for (int k0 = 0; k0 < D; k0 += BK) {
        // --- load A tile (gathered rows), 128x16, transposed into As[k][m] ---
#pragma unroll
        for (int l = 0; l < 2; l++) {
            int slot = tid + l * 256;        // 0..511
            int r = slot >> 2;               // 0..127
            int c = (slot & 3) << 2;         // 0,4,8,12
            int t = sTok[r];
            float4 v = make_float4(0.f, 0.f, 0.f, 0.f);
            if (t >= 0)
                v = *reinterpret_cast<const float4*>(x + (size_t)t * D + k0 + c);
            As[c + 0][r] = v.x;
            As[c + 1][r] = v.y;
            As[c + 2][r] = v.z;
            As[c + 3][r] = v.w;
        }
        // --- load B tile, 16x128, contiguous ---
#pragma unroll
        for (int l = 0; l < 2; l++) {
            int slot = tid + l * 256;
            int kk = slot >> 5;              // 0..15
            int c  = (slot & 31) << 2;       // 0..124
            *reinterpret_cast<float4*>(&Bs[kk][c]) =
                *reinterpret_cast<const float4*>(W + (size_t)(k0 + kk) * H + n0 + c);
        }
        __syncthreads();

#pragma unroll
        for (int kk = 0; kk < BK; kk++) {
            float a[8], b[8];
            *reinterpret_cast<float4*>(&a[0]) = *reinterpret_cast<const float4*>(&As[kk][ty * 8]);
            *reinterpret_cast<float4*>(&a[4]) = *reinterpret_cast<const float4*>(&As[kk][ty * 8 + 4]);
            *reinterpret_cast<float4*>(&b[0]) = *reinterpret_cast<const float4*>(&Bs[kk][tx * 8]);
            *reinterpret_cast<float4*>(&b[4]) = *reinterpret_cast<const float4*>(&Bs[kk][tx * 8 + 4]);
#pragma unroll
            for (int i = 0; i < 8; i++)
#pragma unroll
                for (int j = 0; j < 8; j++)
                    acc[i][j] = fmaf(a[i], b[j], acc[i][j]);
        }
        __syncthreads();
    }

    // --- epilogue ---
    float bias[8];
#pragma unroll
    for (int j = 0; j < 8; j++)
        bias[j] = eb[(size_t)e * H + n0 + tx * 8 + j];

#pragma unroll
    for (int i = 0; i < 8; i++) {
        int r = ty * 8 + i;
        if (r < rows) {
            int t = sTok[r];
            float p = sP[r];
            float* orow = out + (size_t)t * H + n0 + tx * 8;
#pragma unroll
            for (int j = 0; j < 8; j++)
                atomicAdd(&orow[j], p * (acc[i][j] + bias[j]));
        }
    }
}

// ---------------------------------------------------------------------------
extern "C" void kernel_launch(void* const* d_in, const int* in_sizes, int n_in,
                              void* d_out, int out_size) {
    const float* x  = (const float*)d_in[0];   // [N, D]
    const float* gw = (const float*)d_in[1];   // [D, E]
    const float* gb = (const float*)d_in[2];   // [E]
    const float* ew = (const float*)d_in[3];   // [E, D, H]
    const float* eb = (const float*)d_in[4];   // [E, H]
    float* out = (float*)d_out;

    const int E = in_sizes[2];                 // 8
    const int D = in_sizes[1] / E;             // 1024
    const int N = in_sizes[0] / D;             // 16384
    const int H = in_sizes[4] / E;             // 1024

    // 1) zero the [N,H] output region (we accumulate into it)
    size_t n4 = ((size_t)N * (size_t)H) / 4;
    zero_out_kernel<<<512, 256>>>(out, n4);

    // 2) reset counters
    init_kernel<<<1, 32>>>();

    // 3) gating: warp per token
    gate_kernel<<<(N + 7) / 8, 256>>>(x, gw, gb, N, D);

    // 4) scan / tile list / aux-loss scalar
    scan_kernel<<<1, 1>>>(out, (long long)out_size, N, H);

    // 5) bucket pairs by expert
    scatter_kernel<<<(N + 255) / 256, 256>>>(N);

    // 6) grouped gather-GEMM
    dim3 grid(H / BN, MAXTILES);
    moe_gemm_kernel<<<grid, 256>>>(x, ew, eb, out, D, H);
}

// round 3
// speedup vs baseline: 3.6911x; 3.6911x over previous
#include <cuda_runtime.h>
#include <cuda_fp16.h>
#include <mma.h>
#include <math.h>
#include <stdint.h>

using namespace nvcuda;

// ===========================================================================
// MoE top-2 layer — fp16 HMMA (wmma m16n16k16) grouped gather-GEMM.
// (tcgen05 is unusable: harness builds via compute_103 PTX, no 'a' features.)
// Pipeline:
//   init -> gate (fp32) -> scan -> scatter -> convert_w (fp32->fp16 copy)
//   -> gather_a (x rows -> fp16, pair order) -> moe_mma (wmma, 128x128x32
//      tiles, cp.async double buffer) -> combine (out[n] = outp[q0]+outp[q1]).
// ===========================================================================

#define NEXP 8
#define TOPK 2
#define MAXN 16384
#define MAXPAIRS (MAXN * TOPK)      // 32768
#define MAXTILES 264
#define BM 128
#define BN 128
#define BK 32
#define D_DIM 1024
#define H_DIM 1024

#define LDA 48     // halves; 96B rows (32B-aligned)
#define LDB 144    // halves; 288B rows
#define LDC 136    // floats; 544B rows

// smem layout (static, 43.5KB < 48KB)
#define SP_OFF 0                       // 128 floats
#define ABUF_OFF 512                   // 2 x 128*48*2 = 24576
#define BBUF_OFF (512 + 24576)         // 2 x 32*144*2 = 18432
#define SMEM_BYTES (512 + 24576 + 18432)   // 43520
#define SC_OFF 512                     // epilogue reuse: 64*136*4 = 34816

// ---- device scratch ----
__device__ int    g_counts[NEXP];
__device__ int    g_cursor[NEXP];
__device__ float  g_ent;
__device__ int    g_topk_idx[MAXPAIRS];
__device__ float  g_topk_p[MAXPAIRS];
__device__ float  g_pairs_prob[MAXPAIRS];
__device__ int    g_pairs_token[MAXPAIRS];
__device__ int    g_pos[MAXPAIRS];
__device__ int    g_tile_e[MAXTILES];
__device__ int    g_tile_start[MAXTILES];
__device__ int    g_tile_rows[MAXTILES];
__device__ int    g_ntiles;
__device__ __half g_Ag[(MAXPAIRS + BM) * D_DIM];   // gathered fp16 A (zero-padded tail)
__device__ __half g_Wf[NEXP * D_DIM * H_DIM];      // fp16 W, native [E][D][H]
__device__ float  g_outp[MAXPAIRS * H_DIM];        // permuted scaled outputs

// ---------------------------------------------------------------------------
__device__ __forceinline__ uint32_t smem_u32(const void* p) {
    uint32_t a;
    asm("{ .reg .u64 t; cvta.to.shared.u64 t, %1; cvt.u32.u64 %0, t; }"
        : "=r"(a) : "l"(p));
    return a;
}
__device__ __forceinline__ void cpasync16(uint32_t saddr, const void* gptr) {
    asm volatile("cp.async.cg.shared.global [%0], [%1], 16;"
                 :: "r"(saddr), "l"(gptr));
}
#define CP_COMMIT() asm volatile("cp.async.commit_group;" ::: "memory")
#define CP_WAIT(n)  asm volatile("cp.async.wait_group %0;" :: "n"(n) : "memory")

// ---------------------------------------------------------------------------
__global__ void init_kernel() {
    int t = threadIdx.x;
    if (t < NEXP) g_counts[t] = 0;
    if (t == 0) g_ent = 0.f;
}

// ---------------------------------------------------------------------------
// Gating: one warp per token (fp32, identical routing to reference).
__global__ void gate_kernel(const float* __restrict__ x,
                            const float* __restrict__ gw,
                            const float* __restrict__ gb, int N, int D) {
    __shared__ int   s_cnt[NEXP];
    __shared__ float s_ent;
    int tid = threadIdx.x;
    if (tid < NEXP) s_cnt[tid] = 0;
    if (tid == 0) s_ent = 0.f;
    __syncthreads();

    int warp = tid >> 5, lane = tid & 31;
    int token = blockIdx.x * (blockDim.x >> 5) + warp;
    if (token < N) {
        float acc[NEXP];
#pragma unroll
        for (int e = 0; e < NEXP; e++) acc[e] = 0.f;
        const float* xr = x + (size_t)token * D;
        for (int d = lane; d < D; d += 32) {
            float xv = xr[d];
            const float4* g4 = reinterpret_cast<const float4*>(gw + (size_t)d * NEXP);
            float4 a = g4[0], b = g4[1];
            acc[0] += xv * a.x; acc[1] += xv * a.y;
            acc[2] += xv * a.z; acc[3] += xv * a.w;
            acc[4] += xv * b.x; acc[5] += xv * b.y;
            acc[6] += xv * b.z; acc[7] += xv * b.w;
        }
#pragma unroll
        for (int off = 16; off > 0; off >>= 1)
#pragma unroll
            for (int e = 0; e < NEXP; e++)
                acc[e] += __shfl_xor_sync(0xffffffffu, acc[e], off);
        if (lane == 0) {
            float l[NEXP];
            float mx = -1e30f;
#pragma unroll
            for (int e = 0; e < NEXP; e++) { l[e] = acc[e] + gb[e]; mx = fmaxf(mx, l[e]); }
            float sum = 0.f;
#pragma unroll
            for (int e = 0; e < NEXP; e++) { l[e] = __expf(l[e] - mx); sum += l[e]; }
            float inv = 1.f / sum;
            float ent = 0.f;
#pragma unroll
            for (int e = 0; e < NEXP; e++) {
                l[e] *= inv;
                ent -= l[e] * logf(l[e] + 1e-10f);
            }
            int i0 = 0; float p0 = l[0];
#pragma unroll
            for (int e = 1; e < NEXP; e++) if (l[e] > p0) { p0 = l[e]; i0 = e; }
            int i1 = (i0 == 0) ? 1 : 0; float p1 = l[i1];
#pragma unroll
            for (int e = 0; e < NEXP; e++)
                if (e != i0 && l[e] > p1) { p1 = l[e]; i1 = e; }

            g_topk_idx[2 * token + 0] = i0;
            g_topk_idx[2 * token + 1] = i1;
            g_topk_p[2 * token + 0] = p0;
            g_topk_p[2 * token + 1] = p1;
            atomicAdd(&s_cnt[i0], 1);
            atomicAdd(&s_cnt[i1], 1);
            atomicAdd(&s_ent, ent);
        }
    }
    __syncthreads();
    if (tid < NEXP && s_cnt[tid] > 0) atomicAdd(&g_counts[tid], s_cnt[tid]);
    if (tid == 0 && s_ent != 0.f) atomicAdd(&g_ent, s_ent);
}

// ---------------------------------------------------------------------------
__global__ void scan_kernel(float* __restrict__ out, long long out_size, int N) {
    if (threadIdx.x != 0 || blockIdx.x != 0) return;
    int off = 0, nt = 0;
    for (int e = 0; e < NEXP; e++) {
        g_cursor[e] = off;
        int c = g_counts[e];
        for (int s = 0; s < c; s += BM) {
            g_tile_e[nt] = e;
            g_tile_start[nt] = off + s;
            g_tile_rows[nt] = (c - s < BM) ? (c - s) : BM;
            nt++;
        }
        off += c;
    }
    g_ntiles = nt;

    float loss = 0.1f * (g_ent / (float)N);
    for (int e = 0; e < NEXP; e++) {
        float u = (float)g_counts[e] / (float)N - 0.3f;
        if (u > 0.f) loss += u;
    }
    if (out_size > (long long)N * (long long)H_DIM)
        out[out_size - 1] = loss;
}

// ---------------------------------------------------------------------------
__global__ void scatter_kernel(int N) {
    int n = blockIdx.x * blockDim.x + threadIdx.x;
    if (n >= N) return;
#pragma unroll
    for (int k = 0; k < TOPK; k++) {
        int e = g_topk_idx[2 * n + k];
        int pos = atomicAdd(&g_cursor[e], 1);
        g_pairs_token[pos] = n;
        g_pairs_prob[pos] = g_topk_p[2 * n + k];
        g_pos[2 * n + k] = pos;
    }
}

// ---------------------------------------------------------------------------
// W [E][D][H] fp32 -> fp16 (no transpose needed for row-major wmma B).
__global__ void convert_w_kernel(const float* __restrict__ ew, size_t n4) {
    size_t i = (size_t)blockIdx.x * blockDim.x + threadIdx.x;
    size_t stride = (size_t)gridDim.x * blockDim.x;
    const float4* src = reinterpret_cast<const float4*>(ew);
    uint2* dst = reinterpret_cast<uint2*>(g_Wf);
    for (; i < n4; i += stride) {
        float4 v = src[i];
        __half2 lo = __floats2half2_rn(v.x, v.y);
        __half2 hi = __floats2half2_rn(v.z, v.w);
        uint2 o;
        o.x = *reinterpret_cast<uint32_t*>(&lo);
        o.y = *reinterpret_cast<uint32_t*>(&hi);
        dst[i] = o;
    }
}

// ---------------------------------------------------------------------------
// Gather token rows in pair order, fp32 -> fp16.
__global__ void gather_a_kernel(const float* __restrict__ x, int P) {
    int p = blockIdx.x;
    if (p >= P) return;
    int t = g_pairs_token[p];
    const float4* src = reinterpret_cast<const float4*>(x + (size_t)t * D_DIM);
    uint2* dst = reinterpret_cast<uint2*>(g_Ag + (size_t)p * D_DIM);
    float4 v = src[threadIdx.x];
    __half2 lo = __floats2half2_rn(v.x, v.y);
    __half2 hi = __floats2half2_rn(v.z, v.w);
    uint2 o;
    o.x = *reinterpret_cast<uint32_t*>(&lo);
    o.y = *reinterpret_cast<uint32_t*>(&hi);
    dst[threadIdx.x] = o;
}

// ---------------------------------------------------------------------------
// Grouped GEMM: 128(pairs) x 128(H) tile, K=1024, fp16 wmma, fp32 accum.
// 8 warps: warp_m = wid&3 (4 x 32 rows), warp_n = wid>>2 (2 x 64 cols).
// ---------------------------------------------------------------------------
__global__ void __launch_bounds__(256)
moe_mma_kernel(const float* __restrict__ eb) {
    __shared__ __align__(32) char smem[SMEM_BYTES];

    const int rt = blockIdx.y;
    if (rt >= g_ntiles) return;
    const int e     = g_tile_e[rt];
    const int start = g_tile_start[rt];
    const int rows  = g_tile_rows[rt];
    const int n0    = blockIdx.x * BN;

    const int tid = threadIdx.x, wid = tid >> 5;
    const int wm = wid & 3, wn = wid >> 2;
    const uint32_t sb = smem_u32(smem);

    float* sP = reinterpret_cast<float*>(smem + SP_OFF);
    if (tid < BM) sP[tid] = (tid < rows) ? g_pairs_prob[start + tid] : 0.f;

    const __half* Asrc = g_Ag + (size_t)start * D_DIM;
    const __half* Bsrc = g_Wf + (size_t)e * D_DIM * H_DIM + n0;

    wmma::fragment<wmma::accumulator, 16, 16, 16, float> acc[2][4];
#pragma unroll
    for (int i = 0; i < 2; i++)
#pragma unroll
        for (int j = 0; j < 4; j++) wmma::fill_fragment(acc[i][j], 0.f);

    const int NCH = D_DIM / BK;   // 32

    // ---- tile loader: A 128x32 halves, B 32x128 halves ----
    auto load_tile = [&](int ch) {
        const int b = ch & 1;
        const int k0 = ch * BK;
        const uint32_t ab = sb + ABUF_OFF + b * (BM * LDA * 2);
        const uint32_t bb = sb + BBUF_OFF + b * (BK * LDB * 2);
        // A: 128 rows x 4 chunks(16B) = 512 -> 2 per thread
#pragma unroll
        for (int pass = 0; pass < 2; pass++) {
            int idx = tid + pass * 256;
            int r = idx >> 2, c = (idx & 3) * 8;             // halves
            cpasync16(ab + (r * LDA + c) * 2,
                      Asrc + (size_t)r * D_DIM + k0 + c);
        }
        // B: 32 rows x 16 chunks = 512 -> 2 per thread
#pragma unroll
        for (int pass = 0; pass < 2; pass++) {
            int idx = tid + pass * 256;
            int r = idx >> 4, c = (idx & 15) * 8;
            cpasync16(bb + (r * LDB + c) * 2,
                      Bsrc + (size_t)(k0 + r) * H_DIM + c);
        }
        CP_COMMIT();
    };

    load_tile(0);
    for (int ch = 0; ch < NCH; ch++) {
        if (ch + 1 < NCH) load_tile(ch + 1);
        if (ch + 1 < NCH) { CP_WAIT(1); } else { CP_WAIT(0); }
        __syncthreads();

        const int b = ch & 1;
        const __half* Ab = reinterpret_cast<const __half*>(smem + ABUF_OFF + b * (BM * LDA * 2));
        const __half* Bb = reinterpret_cast<const __half*>(smem + BBUF_OFF + b * (BK * LDB * 2));
#pragma unroll
        for (int kk = 0; kk < BK; kk += 16) {
            wmma::fragment<wmma::matrix_a, 16, 16, 16, __half, wmma::row_major> af[2];
            wmma::fragment<wmma::matrix_b, 16, 16, 16, __half, wmma::row_major> bf[4];
#pragma unroll
            for (int i = 0; i < 2; i++)
                wmma::load_matrix_sync(af[i], Ab + (wm * 32 + i * 16) * LDA + kk, LDA);
#pragma unroll
            for (int j = 0; j < 4; j++)
                wmma::load_matrix_sync(bf[j], Bb + kk * LDB + wn * 64 + j * 16, LDB);
#pragma unroll
            for (int i = 0; i < 2; i++)
#pragma unroll
                for (int j = 0; j < 4; j++)
                    wmma::mma_sync(acc[i][j], af[i], bf[j], acc[i][j]);
        }
        __syncthreads();
    }

    // ---- epilogue: two row-half passes through smem (reuses load buffers) ----
    float* sC = reinterpret_cast<float*>(smem + SC_OFF);   // [64][LDC]
    const float* biasrow = eb + (size_t)e * H_DIM + n0;

#pragma unroll
    for (int h = 0; h < 2; h++) {
        if ((wm >> 1) == h) {
            int rloc = (wm & 1) * 32;
#pragma unroll
            for (int i = 0; i < 2; i++)
#pragma unroll
                for (int j = 0; j < 4; j++)
                    wmma::store_matrix_sync(sC + (rloc + i * 16) * LDC + wn * 64 + j * 16,
                                            acc[i][j], LDC, wmma::mem_row_major);
        }
        __syncthreads();
        // 256 threads write 64 rows x 128 cols
        int rl = tid >> 2;                  // 0..63
        int cq = (tid & 3) * 32;            // col quarter
        int r = h * 64 + rl;
        if (r < rows) {
            float p = sP[r];
            float* dst = g_outp + (size_t)(start + r) * H_DIM + n0 + cq;
            const float* brow = biasrow + cq;
            const float* srow = sC + rl * LDC + cq;
#pragma unroll
            for (int c4 = 0; c4 < 8; c4++) {
                float4 bv = reinterpret_cast<const float4*>(brow)[c4];
                float4 o;
                o.x = p * (srow[c4 * 4 + 0] + bv.x);
                o.y = p * (srow[c4 * 4 + 1] + bv.y);
                o.z = p * (srow[c4 * 4 + 2] + bv.z);
                o.w = p * (srow[c4 * 4 + 3] + bv.w);
                reinterpret_cast<float4*>(dst)[c4] = o;
            }
        }
        __syncthreads();
    }
}

// ---------------------------------------------------------------------------
__global__ void combine_kernel(float* __restrict__ out, int N) {
    int n = blockIdx.x;
    if (n >= N) return;
    int c = threadIdx.x;
    int q0 = g_pos[2 * n + 0];
    int q1 = g_pos[2 * n + 1];
    float4 a = reinterpret_cast<const float4*>(g_outp + (size_t)q0 * H_DIM)[c];
    float4 b = reinterpret_cast<const float4*>(g_outp + (size_t)q1 * H_DIM)[c];
    float4 o;
    o.x = a.x + b.x; o.y = a.y + b.y; o.z = a.z + b.z; o.w = a.w + b.w;
    reinterpret_cast<float4*>(out + (size_t)n * H_DIM)[c] = o;
}

// ---------------------------------------------------------------------------
extern "C" void kernel_launch(void* const* d_in, const int* in_sizes, int n_in,
                              void* d_out, int out_size) {
    const float* x  = (const float*)d_in[0];   // [N, D]
    const float* gw = (const float*)d_in[1];   // [D, E]
    const float* gb = (const float*)d_in[2];   // [E]
    const float* ew = (const float*)d_in[3];   // [E, D, H]
    const float* eb = (const float*)d_in[4];   // [E, H]
    float* out = (float*)d_out;

    const int E = in_sizes[2];
    const int D = in_sizes[1] / E;
    const int N = in_sizes[0] / D;
    const int P = N * TOPK;

    init_kernel<<<1, 32>>>();
    gate_kernel<<<(N + 7) / 8, 256>>>(x, gw, gb, N, D);
    scan_kernel<<<1, 1>>>(out, (long long)out_size, N);
    scatter_kernel<<<(N + 255) / 256, 256>>>(N);
    convert_w_kernel<<<2048, 256>>>(ew, (size_t)E * D * H_DIM / 4);
    gather_a_kernel<<<P, 256>>>(x, P);

    dim3 grid(H_DIM / BN, MAXTILES);
    moe_mma_kernel<<<grid, 256>>>(eb);

    combine_kernel<<<N, 256>>>(out, N);
}

// round 4
// speedup vs baseline: 4.5192x; 1.2243x over previous
#include <cuda_runtime.h>
#include <cuda_fp16.h>
#include <mma.h>
#include <math.h>
#include <stdint.h>

using namespace nvcuda;

// ===========================================================================
// MoE top-2 layer — fp16 HMMA grouped GEMM with cp.async.bulk (UBLKCP) loads.
// R3 was LDGSTS-issue-bound (1024 x 16B cp.async per chunk = 2048 issue cyc
// vs 512 tensor cyc). Fix: pre-block A and W into contiguous per-chunk tiles
// (padded, ldmatrix-conflict-free strides) so the mainloop does ONE bulk copy
// per operand per chunk through a 4-stage mbarrier pipeline.
// ===========================================================================

#define NEXP 8
#define TOPK 2
#define MAXN 16384
#define MAXPAIRS (MAXN * TOPK)              // 32768
#define PADPAIRS (MAXPAIRS + NEXP * 128)    // 33792 (expert segs 128-aligned)
#define MAXTILES (PADPAIRS / 128)           // 264
#define BM 128
#define BN 128
#define BK 32
#define D_DIM 1024
#define H_DIM 1024
#define NCH (D_DIM / BK)                    // 32

#define LDA 40                               // halves; 80B rows, conflict-free
#define LDB 136                              // halves; 272B rows, conflict-free
#define LDC 136                              // floats (epilogue staging)
#define ABLK_H (BM * LDA)                    // 5120 halves
#define BBLK_H (BK * LDB)                    // 4352 halves
#define ABLK_BYTES (ABLK_H * 2)              // 10240
#define BBLK_BYTES (BBLK_H * 2)              // 8704
#define STAGES 4
#define STAGE_BYTES (ABLK_BYTES + BBLK_BYTES)  // 18944

// smem layout (dynamic)
#define SP_OFF 0
#define MB_OFF 512
#define STG_OFF 640
#define SMEM_BYTES (STG_OFF + STAGES * STAGE_BYTES)   // 76416

// ---- device scratch ----
__device__ int    g_counts[NEXP];
__device__ int    g_cursor[NEXP];
__device__ float  g_ent;
__device__ int    g_topk_idx[MAXPAIRS];
__device__ float  g_topk_p[MAXPAIRS];
__device__ int    g_pairs_token[PADPAIRS];
__device__ float  g_pairs_prob[PADPAIRS];
__device__ int    g_pos[MAXPAIRS];
__device__ int    g_tile_e[MAXTILES];
__device__ int    g_tile_start[MAXTILES];
__device__ int    g_tile_rows[MAXTILES];
__device__ int    g_ntiles;
__device__ __half g_Ablk[MAXTILES * NCH * ABLK_H];          // blocked fp16 A
__device__ __half g_Wblk[NEXP * (H_DIM / BN) * NCH * BBLK_H]; // blocked fp16 W
__device__ float  g_outp[(size_t)PADPAIRS * H_DIM];

// ---------------------------------------------------------------------------
__device__ __forceinline__ uint32_t smem_u32(const void* p) {
    uint32_t a;
    asm("{ .reg .u64 t; cvta.to.shared.u64 t, %1; cvt.u32.u64 %0, t; }"
        : "=r"(a) : "l"(p));
    return a;
}
#define MB_INIT(mb, c) asm volatile("mbarrier.init.shared.b64 [%0], %1;" :: "r"(mb), "r"(c) : "memory")
#define FENCE_ASYNC()  asm volatile("fence.proxy.async.shared::cta;" ::: "memory")

__device__ __forceinline__ void mb_wait(uint32_t mb, uint32_t parity) {
    uint32_t done;
    asm volatile(
        "{\n\t.reg .pred p;\n\t"
        "mbarrier.try_wait.parity.acquire.cta.shared::cta.b64 p, [%1], %2;\n\t"
        "selp.b32 %0, 1, 0, p;\n\t}"
        : "=r"(done) : "r"(mb), "r"(parity) : "memory");
    if (!done) {
        asm volatile(
            "{\n\t.reg .pred P1;\n\t"
            "W%=:\n\t"
            "mbarrier.try_wait.parity.acquire.cta.shared::cta.b64 P1, [%0], %1, 0x989680;\n\t"
            "@P1 bra.uni D%=;\n\t"
            "bra.uni W%=;\n\t"
            "D%=:\n\t}"
            :: "r"(mb), "r"(parity) : "memory");
    }
}
__device__ __forceinline__ void bulk_ld(uint32_t dst, const void* src,
                                        uint32_t bytes, uint32_t mb) {
    asm volatile(
        "cp.async.bulk.shared::cta.global.mbarrier::complete_tx::bytes [%0], [%1], %2, [%3];"
        :: "r"(dst), "l"(src), "r"(bytes), "r"(mb) : "memory");
}
__device__ __forceinline__ void mb_expect(uint32_t mb, uint32_t bytes) {
    asm volatile("mbarrier.arrive.expect_tx.shared.b64 _, [%0], %1;"
                 :: "r"(mb), "r"(bytes) : "memory");
}

// ---------------------------------------------------------------------------
__global__ void init_kernel(int padp) {
    int i = blockIdx.x * blockDim.x + threadIdx.x;
    if (i < NEXP) g_counts[i] = 0;
    if (i == 0) g_ent = 0.f;
    if (i < padp) g_pairs_token[i] = -1;
}

// ---------------------------------------------------------------------------
// Gating: one warp per token (fp32, identical routing to reference).
__global__ void gate_kernel(const float* __restrict__ x,
                            const float* __restrict__ gw,
                            const float* __restrict__ gb, int N, int D) {
    __shared__ int   s_cnt[NEXP];
    __shared__ float s_ent;
    int tid = threadIdx.x;
    if (tid < NEXP) s_cnt[tid] = 0;
    if (tid == 0) s_ent = 0.f;
    __syncthreads();

    int warp = tid >> 5, lane = tid & 31;
    int token = blockIdx.x * (blockDim.x >> 5) + warp;
    if (token < N) {
        float acc[NEXP];
#pragma unroll
        for (int e = 0; e < NEXP; e++) acc[e] = 0.f;
        const float* xr = x + (size_t)token * D;
        for (int d = lane; d < D; d += 32) {
            float xv = xr[d];
            const float4* g4 = reinterpret_cast<const float4*>(gw + (size_t)d * NEXP);
            float4 a = g4[0], b = g4[1];
            acc[0] += xv * a.x; acc[1] += xv * a.y;
            acc[2] += xv * a.z; acc[3] += xv * a.w;
            acc[4] += xv * b.x; acc[5] += xv * b.y;
            acc[6] += xv * b.z; acc[7] += xv * b.w;
        }
#pragma unroll
        for (int off = 16; off > 0; off >>= 1)
#pragma unroll
            for (int e = 0; e < NEXP; e++)
                acc[e] += __shfl_xor_sync(0xffffffffu, acc[e], off);
        if (lane == 0) {
            float l[NEXP];
            float mx = -1e30f;
#pragma unroll
            for (int e = 0; e < NEXP; e++) { l[e] = acc[e] + gb[e]; mx = fmaxf(mx, l[e]); }
            float sum = 0.f;
#pragma unroll
            for (int e = 0; e < NEXP; e++) { l[e] = __expf(l[e] - mx); sum += l[e]; }
            float inv = 1.f / sum;
            float ent = 0.f;
#pragma unroll
            for (int e = 0; e < NEXP; e++) {
                l[e] *= inv;
                ent -= l[e] * logf(l[e] + 1e-10f);
            }
            int i0 = 0; float p0 = l[0];
#pragma unroll
            for (int e = 1; e < NEXP; e++) if (l[e] > p0) { p0 = l[e]; i0 = e; }
            int i1 = (i0 == 0) ? 1 : 0; float p1 = l[i1];
#pragma unroll
            for (int e = 0; e < NEXP; e++)
                if (e != i0 && l[e] > p1) { p1 = l[e]; i1 = e; }

            g_topk_idx[2 * token + 0] = i0;
            g_topk_idx[2 * token + 1] = i1;
            g_topk_p[2 * token + 0] = p0;
            g_topk_p[2 * token + 1] = p1;
            atomicAdd(&s_cnt[i0], 1);
            atomicAdd(&s_cnt[i1], 1);
            atomicAdd(&s_ent, ent);
        }
    }
    __syncthreads();
    if (tid < NEXP && s_cnt[tid] > 0) atomicAdd(&g_counts[tid], s_cnt[tid]);
    if (tid == 0 && s_ent != 0.f) atomicAdd(&g_ent, s_ent);
}

// ---------------------------------------------------------------------------
// Parallel scan: 128-aligned expert segments, tile list, aux loss.
__global__ void scan_kernel(float* __restrict__ out, long long out_size, int N) {
    __shared__ int s_base[NEXP], s_tb[NEXP], s_cnt[NEXP];
    int tid = threadIdx.x;
    if (tid == 0) {
        int off = 0, tb = 0;
        for (int e = 0; e < NEXP; e++) {
            int c = g_counts[e];
            s_base[e] = off; s_tb[e] = tb; s_cnt[e] = c;
            g_cursor[e] = off;
            tb += (c + 127) >> 7;
            off = (off + c + 127) & ~127;
        }
        g_ntiles = tb;

        float loss = 0.1f * (g_ent / (float)N);
        for (int e = 0; e < NEXP; e++) {
            float u = (float)g_counts[e] / (float)N - 0.3f;
            if (u > 0.f) loss += u;
        }
        if (out_size > (long long)N * (long long)H_DIM)
            out[out_size - 1] = loss;
    }
    __syncthreads();
#pragma unroll
    for (int e = 0; e < NEXP; e++) {
        int c = s_cnt[e], nt = (c + 127) >> 7;
        for (int s = tid; s < nt; s += blockDim.x) {
            int idx = s_tb[e] + s;
            g_tile_e[idx] = e;
            g_tile_start[idx] = s_base[e] + s * 128;
            g_tile_rows[idx] = (c - s * 128 < 128) ? (c - s * 128) : 128;
        }
    }
}

// ---------------------------------------------------------------------------
__global__ void scatter_kernel(int N) {
    int n = blockIdx.x * blockDim.x + threadIdx.x;
    if (n >= N) return;
#pragma unroll
    for (int k = 0; k < TOPK; k++) {
        int e = g_topk_idx[2 * n + k];
        int pos = atomicAdd(&g_cursor[e], 1);
        g_pairs_token[pos] = n;
        g_pairs_prob[pos] = g_topk_p[2 * n + k];
        g_pos[2 * n + k] = pos;
    }
}

// ---------------------------------------------------------------------------
// W [E][D][H] fp32 -> blocked fp16 g_Wblk[e][cb][ch][r=d%32][h%128] (LDB pad).
__global__ void convert_w_kernel(const float* __restrict__ ew) {
    // piece = (e, d, pc): pc in [0,128), 8 halves each
    size_t i = (size_t)blockIdx.x * blockDim.x + threadIdx.x;   // [0, 8*1024*128)
    int pc = (int)(i & 127);
    int d  = (int)((i >> 7) & 1023);
    int e  = (int)(i >> 17);
    const float* src = ew + ((size_t)e * D_DIM + d) * H_DIM + pc * 8;
    int cb = pc >> 4, hl = (pc & 15) * 8;
    __half* dst = g_Wblk + ((size_t)(e * 8 + cb) * NCH + (d >> 5)) * BBLK_H
                + (d & 31) * LDB + hl;
    float4 v0 = reinterpret_cast<const float4*>(src)[0];
    float4 v1 = reinterpret_cast<const float4*>(src)[1];
    __half2 h0 = __floats2half2_rn(v0.x, v0.y);
    __half2 h1 = __floats2half2_rn(v0.z, v0.w);
    __half2 h2 = __floats2half2_rn(v1.x, v1.y);
    __half2 h3 = __floats2half2_rn(v1.z, v1.w);
    uint4 o;
    o.x = *reinterpret_cast<uint32_t*>(&h0);
    o.y = *reinterpret_cast<uint32_t*>(&h1);
    o.z = *reinterpret_cast<uint32_t*>(&h2);
    o.w = *reinterpret_cast<uint32_t*>(&h3);
    *reinterpret_cast<uint4*>(dst) = o;
}

// ---------------------------------------------------------------------------
// Gather token rows -> blocked fp16 g_Ablk[tile][ch][r=slot%128][k%32] (LDA pad).
__global__ void gather_a_kernel(const float* __restrict__ x) {
    int p = blockIdx.x;                       // slot in padded pair array
    int t = g_pairs_token[p];
    if (t < 0) return;
    int tile = p >> 7, row = p & 127;
    int tid = threadIdx.x;                    // 128 threads
    int c = tid >> 2, q = tid & 3;            // chunk, quarter (8 halves)
    const float* src = x + (size_t)t * D_DIM + c * 32 + q * 8;
    float4 v0 = reinterpret_cast<const float4*>(src)[0];
    float4 v1 = reinterpret_cast<const float4*>(src)[1];
    __half2 h0 = __floats2half2_rn(v0.x, v0.y);
    __half2 h1 = __floats2half2_rn(v0.z, v0.w);
    __half2 h2 = __floats2half2_rn(v1.x, v1.y);
    __half2 h3 = __floats2half2_rn(v1.z, v1.w);
    uint4 o;
    o.x = *reinterpret_cast<uint32_t*>(&h0);
    o.y = *reinterpret_cast<uint32_t*>(&h1);
    o.z = *reinterpret_cast<uint32_t*>(&h2);
    o.w = *reinterpret_cast<uint32_t*>(&h3);
    __half* dst = g_Ablk + ((size_t)tile * NCH + c) * ABLK_H + row * LDA + q * 8;
    *reinterpret_cast<uint4*>(dst) = o;
}

// ---------------------------------------------------------------------------
// Grouped GEMM: 128x128 tile, K=1024, fp16 wmma / fp32 acc.
// 4-stage cp.async.bulk pipeline; 2 bulk ops per chunk.
// ---------------------------------------------------------------------------
__global__ void __launch_bounds__(256)
moe_mma_kernel(const float* __restrict__ eb) {
    extern __shared__ __align__(128) char smem[];

    const int rt = blockIdx.y;
    if (rt >= g_ntiles) return;
    const int e     = g_tile_e[rt];
    const int start = g_tile_start[rt];      // 128-aligned
    const int rows  = g_tile_rows[rt];
    const int cb    = blockIdx.x;
    const int n0    = cb * BN;
    const int tile  = start >> 7;

    const int tid = threadIdx.x, wid = tid >> 5;
    const int wm = wid & 3, wn = wid >> 2;
    const uint32_t sb = smem_u32(smem);

    float* sP = reinterpret_cast<float*>(smem + SP_OFF);
    if (tid < BM) sP[tid] = (tid < rows) ? g_pairs_prob[start + tid] : 0.f;

    if (tid == 0)
#pragma unroll
        for (int s = 0; s < STAGES; s++) MB_INIT(sb + MB_OFF + s * 8, 1);
    __syncthreads();
    FENCE_ASYNC();

    const __half* Asrc = g_Ablk + (size_t)tile * NCH * ABLK_H;
    const __half* Bsrc = g_Wblk + (size_t)(e * 8 + cb) * NCH * BBLK_H;

    if (tid == 0) {
#pragma unroll
        for (int ch = 0; ch < STAGES; ch++) {
            int s = ch;
            uint32_t mb = sb + MB_OFF + s * 8;
            uint32_t stg = sb + STG_OFF + s * STAGE_BYTES;
            mb_expect(mb, STAGE_BYTES);
            bulk_ld(stg, Asrc + (size_t)ch * ABLK_H, ABLK_BYTES, mb);
            bulk_ld(stg + ABLK_BYTES, Bsrc + (size_t)ch * BBLK_H, BBLK_BYTES, mb);
        }
    }

    wmma::fragment<wmma::accumulator, 16, 16, 16, float> acc[2][4];
#pragma unroll
    for (int i = 0; i < 2; i++)
#pragma unroll
        for (int j = 0; j < 4; j++) wmma::fill_fragment(acc[i][j], 0.f);

    for (int ch = 0; ch < NCH; ch++) {
        const int s = ch & (STAGES - 1);
        mb_wait(sb + MB_OFF + s * 8, (ch >> 2) & 1);

        const __half* Ab = reinterpret_cast<const __half*>(smem + STG_OFF + s * STAGE_BYTES);
        const __half* Bb = reinterpret_cast<const __half*>(smem + STG_OFF + s * STAGE_BYTES + ABLK_BYTES);
#pragma unroll
        for (int kk = 0; kk < BK; kk += 16) {
            wmma::fragment<wmma::matrix_a, 16, 16, 16, __half, wmma::row_major> af[2];
            wmma::fragment<wmma::matrix_b, 16, 16, 16, __half, wmma::row_major> bf[4];
#pragma unroll
            for (int i = 0; i < 2; i++)
                wmma::load_matrix_sync(af[i], Ab + (wm * 32 + i * 16) * LDA + kk, LDA);
#pragma unroll
            for (int j = 0; j < 4; j++)
                wmma::load_matrix_sync(bf[j], Bb + kk * LDB + wn * 64 + j * 16, LDB);
#pragma unroll
            for (int i = 0; i < 2; i++)
#pragma unroll
                for (int j = 0; j < 4; j++)
                    wmma::mma_sync(acc[i][j], af[i], bf[j], acc[i][j]);
        }
        __syncthreads();
        if (ch + STAGES < NCH && tid == 0) {
            uint32_t mb = sb + MB_OFF + s * 8;
            uint32_t stg = sb + STG_OFF + s * STAGE_BYTES;
            mb_expect(mb, STAGE_BYTES);
            bulk_ld(stg, Asrc + (size_t)(ch + STAGES) * ABLK_H, ABLK_BYTES, mb);
            bulk_ld(stg + ABLK_BYTES, Bsrc + (size_t)(ch + STAGES) * BBLK_H, BBLK_BYTES, mb);
        }
    }

    // ---- epilogue: two row-half passes via smem staging ----
    float* sC = reinterpret_cast<float*>(smem + STG_OFF);   // [64][LDC]
    const float* biasrow = eb + (size_t)e * H_DIM + n0;

#pragma unroll
    for (int h = 0; h < 2; h++) {
        if ((wm >> 1) == h) {
            int rloc = (wm & 1) * 32;
#pragma unroll
            for (int i = 0; i < 2; i++)
#pragma unroll
                for (int j = 0; j < 4; j++)
                    wmma::store_matrix_sync(sC + (rloc + i * 16) * LDC + wn * 64 + j * 16,
                                            acc[i][j], LDC, wmma::mem_row_major);
        }
        __syncthreads();
        int rl = tid >> 2;
        int cq = (tid & 3) * 32;
        int r = h * 64 + rl;
        if (r < rows) {
            float p = sP[r];
            float* dst = g_outp + (size_t)(start + r) * H_DIM + n0 + cq;
            const float* brow = biasrow + cq;
            const float* srow = sC + rl * LDC + cq;
#pragma unroll
            for (int c4 = 0; c4 < 8; c4++) {
                float4 bv = reinterpret_cast<const float4*>(brow)[c4];
                float4 o;
                o.x = p * (srow[c4 * 4 + 0] + bv.x);
                o.y = p * (srow[c4 * 4 + 1] + bv.y);
                o.z = p * (srow[c4 * 4 + 2] + bv.z);
                o.w = p * (srow[c4 * 4 + 3] + bv.w);
                reinterpret_cast<float4*>(dst)[c4] = o;
            }
        }
        __syncthreads();
    }
}

// ---------------------------------------------------------------------------
__global__ void combine_kernel(float* __restrict__ out, int N) {
    int n = blockIdx.x;
    if (n >= N) return;
    int c = threadIdx.x;
    int q0 = g_pos[2 * n + 0];
    int q1 = g_pos[2 * n + 1];
    float4 a = reinterpret_cast<const float4*>(g_outp + (size_t)q0 * H_DIM)[c];
    float4 b = reinterpret_cast<const float4*>(g_outp + (size_t)q1 * H_DIM)[c];
    float4 o;
    o.x = a.x + b.x; o.y = a.y + b.y; o.z = a.z + b.z; o.w = a.w + b.w;
    reinterpret_cast<float4*>(out + (size_t)n * H_DIM)[c] = o;
}

// ---------------------------------------------------------------------------
extern "C" void kernel_launch(void* const* d_in, const int* in_sizes, int n_in,
                              void* d_out, int out_size) {
    const float* x  = (const float*)d_in[0];   // [N, D]
    const float* gw = (const float*)d_in[1];   // [D, E]
    const float* gb = (const float*)d_in[2];   // [E]
    const float* ew = (const float*)d_in[3];   // [E, D, H]
    const float* eb = (const float*)d_in[4];   // [E, H]
    float* out = (float*)d_out;

    const int E = in_sizes[2];
    const int D = in_sizes[1] / E;
    const int N = in_sizes[0] / D;

    cudaFuncSetAttribute(moe_mma_kernel,
                         cudaFuncAttributeMaxDynamicSharedMemorySize, SMEM_BYTES);

    init_kernel<<<(PADPAIRS + 255) / 256, 256>>>(PADPAIRS);
    gate_kernel<<<(N + 7) / 8, 256>>>(x, gw, gb, N, D);
    scan_kernel<<<1, 256>>>(out, (long long)out_size, N);
    scatter_kernel<<<(N + 255) / 256, 256>>>(N);
    convert_w_kernel<<<4096, 256>>>(ew);
    gather_a_kernel<<<PADPAIRS, 128>>>(x);

    dim3 grid(H_DIM / BN, MAXTILES);
    moe_mma_kernel<<<grid, 256, SMEM_BYTES>>>(eb);

    combine_kernel<<<N, 256>>>(out, N);
}

// round 5
// speedup vs baseline: 5.0057x; 1.1077x over previous
#include <cuda_runtime.h>
#include <cuda_fp16.h>
#include <mma.h>
#include <math.h>
#include <stdint.h>

using namespace nvcuda;

// ===========================================================================
// MoE top-2 layer — fp16 HMMA grouped GEMM, cp.async.bulk pipeline.
// R5: force 2 CTAs/SM on the MMA kernel (__launch_bounds__(256,2)),
//     fp16 permuted-output intermediate (halves epilogue+combine traffic),
//     block-aggregated scatter, init fused into convert_w.
// ===========================================================================

#define NEXP 8
#define TOPK 2
#define MAXN 16384
#define MAXPAIRS (MAXN * TOPK)              // 32768
#define PADPAIRS (MAXPAIRS + NEXP * 128)    // 33792 (expert segs 128-aligned)
#define MAXTILES (PADPAIRS / 128)           // 264
#define BM 128
#define BN 128
#define BK 32
#define D_DIM 1024
#define H_DIM 1024
#define NCH (D_DIM / BK)                    // 32

#define LDA 40                               // halves; 80B rows
#define LDB 136                              // halves; 272B rows
#define LDC 136                              // floats (epilogue staging)
#define ABLK_H (BM * LDA)                    // 5120 halves
#define BBLK_H (BK * LDB)                    // 4352 halves
#define ABLK_BYTES (ABLK_H * 2)
#define BBLK_BYTES (BBLK_H * 2)
#define STAGES 4
#define STAGE_BYTES (ABLK_BYTES + BBLK_BYTES)  // 18944

#define SP_OFF 0
#define MB_OFF 512
#define STG_OFF 640
#define SMEM_BYTES (STG_OFF + STAGES * STAGE_BYTES)   // 76416

// ---- device scratch ----
__device__ int    g_counts[NEXP];
__device__ int    g_cursor[NEXP];
__device__ float  g_ent;
__device__ int    g_topk_idx[MAXPAIRS];
__device__ float  g_topk_p[MAXPAIRS];
__device__ int    g_pairs_token[PADPAIRS];
__device__ float  g_pairs_prob[PADPAIRS];
__device__ int    g_pos[MAXPAIRS];
__device__ int    g_tile_e[MAXTILES];
__device__ int    g_tile_start[MAXTILES];
__device__ int    g_tile_rows[MAXTILES];
__device__ int    g_ntiles;
__device__ __half g_Ablk[MAXTILES * NCH * ABLK_H];
__device__ __half g_Wblk[NEXP * (H_DIM / BN) * NCH * BBLK_H];
__device__ __half g_outp[(size_t)PADPAIRS * H_DIM];      // fp16 permuted outputs

// ---------------------------------------------------------------------------
__device__ __forceinline__ uint32_t smem_u32(const void* p) {
    uint32_t a;
    asm("{ .reg .u64 t; cvta.to.shared.u64 t, %1; cvt.u32.u64 %0, t; }"
        : "=r"(a) : "l"(p));
    return a;
}
#define MB_INIT(mb, c) asm volatile("mbarrier.init.shared.b64 [%0], %1;" :: "r"(mb), "r"(c) : "memory")
#define FENCE_ASYNC()  asm volatile("fence.proxy.async.shared::cta;" ::: "memory")

__device__ __forceinline__ void mb_wait(uint32_t mb, uint32_t parity) {
    uint32_t done;
    asm volatile(
        "{\n\t.reg .pred p;\n\t"
        "mbarrier.try_wait.parity.acquire.cta.shared::cta.b64 p, [%1], %2;\n\t"
        "selp.b32 %0, 1, 0, p;\n\t}"
        : "=r"(done) : "r"(mb), "r"(parity) : "memory");
    if (!done) {
        asm volatile(
            "{\n\t.reg .pred P1;\n\t"
            "W%=:\n\t"
            "mbarrier.try_wait.parity.acquire.cta.shared::cta.b64 P1, [%0], %1, 0x989680;\n\t"
            "@P1 bra.uni D%=;\n\t"
            "bra.uni W%=;\n\t"
            "D%=:\n\t}"
            :: "r"(mb), "r"(parity) : "memory");
    }
}
__device__ __forceinline__ void bulk_ld(uint32_t dst, const void* src,
                                        uint32_t bytes, uint32_t mb) {
    asm volatile(
        "cp.async.bulk.shared::cta.global.mbarrier::complete_tx::bytes [%0], [%1], %2, [%3];"
        :: "r"(dst), "l"(src), "r"(bytes), "r"(mb) : "memory");
}
__device__ __forceinline__ void mb_expect(uint32_t mb, uint32_t bytes) {
    asm volatile("mbarrier.arrive.expect_tx.shared.b64 _, [%0], %1;"
                 :: "r"(mb), "r"(bytes) : "memory");
}

// ---------------------------------------------------------------------------
// W [E][D][H] fp32 -> blocked fp16 g_Wblk; also fused global init.
__global__ void convert_w_kernel(const float* __restrict__ ew) {
    size_t i = (size_t)blockIdx.x * blockDim.x + threadIdx.x;   // [0, 8*1024*128)
    if (i < NEXP) g_counts[i] = 0;
    if (i == 0) g_ent = 0.f;
    if (i < PADPAIRS) g_pairs_token[i] = -1;

    int pc = (int)(i & 127);
    int d  = (int)((i >> 7) & 1023);
    int e  = (int)(i >> 17);
    const float* src = ew + ((size_t)e * D_DIM + d) * H_DIM + pc * 8;
    int cb = pc >> 4, hl = (pc & 15) * 8;
    __half* dst = g_Wblk + ((size_t)(e * 8 + cb) * NCH + (d >> 5)) * BBLK_H
                + (d & 31) * LDB + hl;
    float4 v0 = reinterpret_cast<const float4*>(src)[0];
    float4 v1 = reinterpret_cast<const float4*>(src)[1];
    __half2 h0 = __floats2half2_rn(v0.x, v0.y);
    __half2 h1 = __floats2half2_rn(v0.z, v0.w);
    __half2 h2 = __floats2half2_rn(v1.x, v1.y);
    __half2 h3 = __floats2half2_rn(v1.z, v1.w);
    uint4 o;
    o.x = *reinterpret_cast<uint32_t*>(&h0);
    o.y = *reinterpret_cast<uint32_t*>(&h1);
    o.z = *reinterpret_cast<uint32_t*>(&h2);
    o.w = *reinterpret_cast<uint32_t*>(&h3);
    *reinterpret_cast<uint4*>(dst) = o;
}

// ---------------------------------------------------------------------------
// Gating: one warp per token (fp32, identical routing to reference).
__global__ void gate_kernel(const float* __restrict__ x,
                            const float* __restrict__ gw,
                            const float* __restrict__ gb, int N, int D) {
    __shared__ int   s_cnt[NEXP];
    __shared__ float s_ent;
    int tid = threadIdx.x;
    if (tid < NEXP) s_cnt[tid] = 0;
    if (tid == 0) s_ent = 0.f;
    __syncthreads();

    int warp = tid >> 5, lane = tid & 31;
    int token = blockIdx.x * (blockDim.x >> 5) + warp;
    if (token < N) {
        float acc[NEXP];
#pragma unroll
        for (int e = 0; e < NEXP; e++) acc[e] = 0.f;
        const float* xr = x + (size_t)token * D;
        for (int d = lane; d < D; d += 32) {
            float xv = xr[d];
            const float4* g4 = reinterpret_cast<const float4*>(gw + (size_t)d * NEXP);
            float4 a = g4[0], b = g4[1];
            acc[0] += xv * a.x; acc[1] += xv * a.y;
            acc[2] += xv * a.z; acc[3] += xv * a.w;
            acc[4] += xv * b.x; acc[5] += xv * b.y;
            acc[6] += xv * b.z; acc[7] += xv * b.w;
        }
#pragma unroll
        for (int off = 16; off > 0; off >>= 1)
#pragma unroll
            for (int e = 0; e < NEXP; e++)
                acc[e] += __shfl_xor_sync(0xffffffffu, acc[e], off);
        if (lane == 0) {
            float l[NEXP];
            float mx = -1e30f;
#pragma unroll
            for (int e = 0; e < NEXP; e++) { l[e] = acc[e] + gb[e]; mx = fmaxf(mx, l[e]); }
            float sum = 0.f;
#pragma unroll
            for (int e = 0; e < NEXP; e++) { l[e] = __expf(l[e] - mx); sum += l[e]; }
            float inv = 1.f / sum;
            float ent = 0.f;
#pragma unroll
            for (int e = 0; e < NEXP; e++) {
                l[e] *= inv;
                ent -= l[e] * logf(l[e] + 1e-10f);
            }
            int i0 = 0; float p0 = l[0];
#pragma unroll
            for (int e = 1; e < NEXP; e++) if (l[e] > p0) { p0 = l[e]; i0 = e; }
            int i1 = (i0 == 0) ? 1 : 0; float p1 = l[i1];
#pragma unroll
            for (int e = 0; e < NEXP; e++)
                if (e != i0 && l[e] > p1) { p1 = l[e]; i1 = e; }

            g_topk_idx[2 * token + 0] = i0;
            g_topk_idx[2 * token + 1] = i1;
            g_topk_p[2 * token + 0] = p0;
            g_topk_p[2 * token + 1] = p1;
            atomicAdd(&s_cnt[i0], 1);
            atomicAdd(&s_cnt[i1], 1);
            atomicAdd(&s_ent, ent);
        }
    }
    __syncthreads();
    if (tid < NEXP && s_cnt[tid] > 0) atomicAdd(&g_counts[tid], s_cnt[tid]);
    if (tid == 0 && s_ent != 0.f) atomicAdd(&g_ent, s_ent);
}

// ---------------------------------------------------------------------------
// Scan: 128-aligned expert segments, tile list, aux loss.
__global__ void scan_kernel(float* __restrict__ out, long long out_size, int N) {
    __shared__ int s_base[NEXP], s_tb[NEXP], s_cnt[NEXP];
    int tid = threadIdx.x;
    if (tid == 0) {
        int off = 0, tb = 0;
        for (int e = 0; e < NEXP; e++) {
            int c = g_counts[e];
            s_base[e] = off; s_tb[e] = tb; s_cnt[e] = c;
            g_cursor[e] = off;
            tb += (c + 127) >> 7;
            off = (off + c + 127) & ~127;
        }
        g_ntiles = tb;

        float loss = 0.1f * (g_ent / (float)N);
        for (int e = 0; e < NEXP; e++) {
            float u = (float)g_counts[e] / (float)N - 0.3f;
            if (u > 0.f) loss += u;
        }
        if (out_size > (long long)N * (long long)H_DIM)
            out[out_size - 1] = loss;
    }
    __syncthreads();
#pragma unroll
    for (int e = 0; e < NEXP; e++) {
        int c = s_cnt[e], nt = (c + 127) >> 7;
        for (int s = tid; s < nt; s += blockDim.x) {
            int idx = s_tb[e] + s;
            g_tile_e[idx] = e;
            g_tile_start[idx] = s_base[e] + s * 128;
            g_tile_rows[idx] = (c - s * 128 < 128) ? (c - s * 128) : 128;
        }
    }
}

// ---------------------------------------------------------------------------
// Block-aggregated scatter: smem histogram, one global atomic per expert/block.
__global__ void scatter_kernel(int N) {
    __shared__ int s_cnt[NEXP], s_base[NEXP];
    int tid = threadIdx.x;
    if (tid < NEXP) s_cnt[tid] = 0;
    __syncthreads();

    int n = blockIdx.x * blockDim.x + tid;
    int e0 = 0, e1 = 0, o0 = 0, o1 = 0;
    bool valid = (n < N);
    if (valid) {
        e0 = g_topk_idx[2 * n + 0];
        e1 = g_topk_idx[2 * n + 1];
        o0 = atomicAdd(&s_cnt[e0], 1);
        o1 = atomicAdd(&s_cnt[e1], 1);
    }
    __syncthreads();
    if (tid < NEXP)
        s_base[tid] = (s_cnt[tid] > 0) ? atomicAdd(&g_cursor[tid], s_cnt[tid]) : 0;
    __syncthreads();
    if (valid) {
        int p0 = s_base[e0] + o0;
        int p1 = s_base[e1] + o1;
        g_pairs_token[p0] = n;
        g_pairs_prob[p0] = g_topk_p[2 * n + 0];
        g_pos[2 * n + 0] = p0;
        g_pairs_token[p1] = n;
        g_pairs_prob[p1] = g_topk_p[2 * n + 1];
        g_pos[2 * n + 1] = p1;
    }
}

// ---------------------------------------------------------------------------
// Gather token rows -> blocked fp16 g_Ablk[tile][ch][row][k%32].
__global__ void gather_a_kernel(const float* __restrict__ x) {
    int p = blockIdx.x;
    int t = g_pairs_token[p];
    if (t < 0) return;
    int tile = p >> 7, row = p & 127;
    int tid = threadIdx.x;                    // 128 threads
    int c = tid >> 2, q = tid & 3;
    const float* src = x + (size_t)t * D_DIM + c * 32 + q * 8;
    float4 v0 = reinterpret_cast<const float4*>(src)[0];
    float4 v1 = reinterpret_cast<const float4*>(src)[1];
    __half2 h0 = __floats2half2_rn(v0.x, v0.y);
    __half2 h1 = __floats2half2_rn(v0.z, v0.w);
    __half2 h2 = __floats2half2_rn(v1.x, v1.y);
    __half2 h3 = __floats2half2_rn(v1.z, v1.w);
    uint4 o;
    o.x = *reinterpret_cast<uint32_t*>(&h0);
    o.y = *reinterpret_cast<uint32_t*>(&h1);
    o.z = *reinterpret_cast<uint32_t*>(&h2);
    o.w = *reinterpret_cast<uint32_t*>(&h3);
    __half* dst = g_Ablk + ((size_t)tile * NCH + c) * ABLK_H + row * LDA + q * 8;
    *reinterpret_cast<uint4*>(dst) = o;
}

// ---------------------------------------------------------------------------
// Grouped GEMM: 128x128 tile, K=1024, fp16 wmma / fp32 acc.
// 4-stage cp.async.bulk pipeline; forced 2 CTAs/SM.
// ---------------------------------------------------------------------------
__global__ void __launch_bounds__(256, 2)
moe_mma_kernel(const float* __restrict__ eb) {
    extern __shared__ __align__(128) char smem[];

    const int rt = blockIdx.y;
    if (rt >= g_ntiles) return;
    const int e     = g_tile_e[rt];
    const int start = g_tile_start[rt];      // 128-aligned
    const int rows  = g_tile_rows[rt];
    const int cb    = blockIdx.x;
    const int n0    = cb * BN;
    const int tile  = start >> 7;

    const int tid = threadIdx.x, wid = tid >> 5;
    const int wm = wid & 3, wn = wid >> 2;
    const uint32_t sb = smem_u32(smem);

    float* sP = reinterpret_cast<float*>(smem + SP_OFF);
    if (tid < BM) sP[tid] = (tid < rows) ? g_pairs_prob[start + tid] : 0.f;

    if (tid == 0)
#pragma unroll
        for (int s = 0; s < STAGES; s++) MB_INIT(sb + MB_OFF + s * 8, 1);
    __syncthreads();
    FENCE_ASYNC();

    const __half* Asrc = g_Ablk + (size_t)tile * NCH * ABLK_H;
    const __half* Bsrc = g_Wblk + (size_t)(e * 8 + cb) * NCH * BBLK_H;

    if (tid == 0) {
#pragma unroll
        for (int ch = 0; ch < STAGES; ch++) {
            uint32_t mb = sb + MB_OFF + ch * 8;
            uint32_t stg = sb + STG_OFF + ch * STAGE_BYTES;
            mb_expect(mb, STAGE_BYTES);
            bulk_ld(stg, Asrc + (size_t)ch * ABLK_H, ABLK_BYTES, mb);
            bulk_ld(stg + ABLK_BYTES, Bsrc + (size_t)ch * BBLK_H, BBLK_BYTES, mb);
        }
    }

    wmma::fragment<wmma::accumulator, 16, 16, 16, float> acc[2][4];
#pragma unroll
    for (int i = 0; i < 2; i++)
#pragma unroll
        for (int j = 0; j < 4; j++) wmma::fill_fragment(acc[i][j], 0.f);

    for (int ch = 0; ch < NCH; ch++) {
        const int s = ch & (STAGES - 1);
        mb_wait(sb + MB_OFF + s * 8, (ch >> 2) & 1);

        const __half* Ab = reinterpret_cast<const __half*>(smem + STG_OFF + s * STAGE_BYTES);
        const __half* Bb = reinterpret_cast<const __half*>(smem + STG_OFF + s * STAGE_BYTES + ABLK_BYTES);
#pragma unroll
        for (int kk = 0; kk < BK; kk += 16) {
            wmma::fragment<wmma::matrix_a, 16, 16, 16, __half, wmma::row_major> af[2];
            wmma::fragment<wmma::matrix_b, 16, 16, 16, __half, wmma::row_major> bf[4];
#pragma unroll
            for (int i = 0; i < 2; i++)
                wmma::load_matrix_sync(af[i], Ab + (wm * 32 + i * 16) * LDA + kk, LDA);
#pragma unroll
            for (int j = 0; j < 4; j++)
                wmma::load_matrix_sync(bf[j], Bb + kk * LDB + wn * 64 + j * 16, LDB);
#pragma unroll
            for (int i = 0; i < 2; i++)
#pragma unroll
                for (int j = 0; j < 4; j++)
                    wmma::mma_sync(acc[i][j], af[i], bf[j], acc[i][j]);
        }
        __syncthreads();
        if (ch + STAGES < NCH && tid == 0) {
            uint32_t mb = sb + MB_OFF + s * 8;
            uint32_t stg = sb + STG_OFF + s * STAGE_BYTES;
            mb_expect(mb, STAGE_BYTES);
            bulk_ld(stg, Asrc + (size_t)(ch + STAGES) * ABLK_H, ABLK_BYTES, mb);
            bulk_ld(stg + ABLK_BYTES, Bsrc + (size_t)(ch + STAGES) * BBLK_H, BBLK_BYTES, mb);
        }
    }

    // ---- epilogue: two row-half passes via smem staging; fp16 output ----
    float* sC = reinterpret_cast<float*>(smem + STG_OFF);   // [64][LDC]
    const float* biasrow = eb + (size_t)e * H_DIM + n0;

#pragma unroll
    for (int h = 0; h < 2; h++) {
        if ((wm >> 1) == h) {
            int rloc = (wm & 1) * 32;
#pragma unroll
            for (int i = 0; i < 2; i++)
#pragma unroll
                for (int j = 0; j < 4; j++)
                    wmma::store_matrix_sync(sC + (rloc + i * 16) * LDC + wn * 64 + j * 16,
                                            acc[i][j], LDC, wmma::mem_row_major);
        }
        __syncthreads();
        int rl = tid >> 2;
        int cq = (tid & 3) * 32;
        int r = h * 64 + rl;
        if (r < rows) {
            float p = sP[r];
            __half* dst = g_outp + (size_t)(start + r) * H_DIM + n0 + cq;
            const float* brow = biasrow + cq;
            const float* srow = sC + rl * LDC + cq;
#pragma unroll
            for (int c8 = 0; c8 < 4; c8++) {
                float4 b0 = reinterpret_cast<const float4*>(brow)[c8 * 2 + 0];
                float4 b1 = reinterpret_cast<const float4*>(brow)[c8 * 2 + 1];
                const float* sv = srow + c8 * 8;
                __half2 h0 = __floats2half2_rn(p * (sv[0] + b0.x), p * (sv[1] + b0.y));
                __half2 h1 = __floats2half2_rn(p * (sv[2] + b0.z), p * (sv[3] + b0.w));
                __half2 h2 = __floats2half2_rn(p * (sv[4] + b1.x), p * (sv[5] + b1.y));
                __half2 h3 = __floats2half2_rn(p * (sv[6] + b1.z), p * (sv[7] + b1.w));
                uint4 o;
                o.x = *reinterpret_cast<uint32_t*>(&h0);
                o.y = *reinterpret_cast<uint32_t*>(&h1);
                o.z = *reinterpret_cast<uint32_t*>(&h2);
                o.w = *reinterpret_cast<uint32_t*>(&h3);
                reinterpret_cast<uint4*>(dst)[c8] = o;
            }
        }
        __syncthreads();
    }
}

// ---------------------------------------------------------------------------
// out[n] = outp[q0] + outp[q1]  (fp16 reads, fp32 sum + store)
__global__ void combine_kernel(float* __restrict__ out, int N) {
    int n = blockIdx.x;
    if (n >= N) return;
    int c = threadIdx.x;                      // 256 threads x 4 elems
    int q0 = g_pos[2 * n + 0];
    int q1 = g_pos[2 * n + 1];
    uint2 a = reinterpret_cast<const uint2*>(g_outp + (size_t)q0 * H_DIM)[c];
    uint2 b = reinterpret_cast<const uint2*>(g_outp + (size_t)q1 * H_DIM)[c];
    float2 a0 = __half22float2(*reinterpret_cast<__half2*>(&a.x));
    float2 a1 = __half22float2(*reinterpret_cast<__half2*>(&a.y));
    float2 b0 = __half22float2(*reinterpret_cast<__half2*>(&b.x));
    float2 b1 = __half22float2(*reinterpret_cast<__half2*>(&b.y));
    float4 o;
    o.x = a0.x + b0.x; o.y = a0.y + b0.y;
    o.z = a1.x + b1.x; o.w = a1.y + b1.y;
    reinterpret_cast<float4*>(out + (size_t)n * H_DIM)[c] = o;
}

// ---------------------------------------------------------------------------
extern "C" void kernel_launch(void* const* d_in, const int* in_sizes, int n_in,
                              void* d_out, int out_size) {
    const float* x  = (const float*)d_in[0];   // [N, D]
    const float* gw = (const float*)d_in[1];   // [D, E]
    const float* gb = (const float*)d_in[2];   // [E]
    const float* ew = (const float*)d_in[3];   // [E, D, H]
    const float* eb = (const float*)d_in[4];   // [E, H]
    float* out = (float*)d_out;

    const int E = in_sizes[2];
    const int D = in_sizes[1] / E;
    const int N = in_sizes[0] / D;

    cudaFuncSetAttribute(moe_mma_kernel,
                         cudaFuncAttributeMaxDynamicSharedMemorySize, SMEM_BYTES);

    convert_w_kernel<<<4096, 256>>>(ew);      // also does global init
    gate_kernel<<<(N + 7) / 8, 256>>>(x, gw, gb, N, D);
    scan_kernel<<<1, 256>>>(out, (long long)out_size, N);
    scatter_kernel<<<(N + 255) / 256, 256>>>(N);
    gather_a_kernel<<<PADPAIRS, 128>>>(x);

    dim3 grid(H_DIM / BN, MAXTILES);
    moe_mma_kernel<<<grid, 256, SMEM_BYTES>>>(eb);

    combine_kernel<<<N, 256>>>(out, N);
}